// round 13
// baseline (speedup 1.0000x reference)
#include <cuda_runtime.h>
#include <cuda_fp16.h>

// MedianBlur: out = x + 0.2*(median3x3(x, zero-pad) - x)
// x: (8, 64, 256, 256) fp32 -> 512 independent 256x256 images.
// Warp = 8-row x 256-col band; lane owns 8 cols. TWO output rows per
// iteration packed vertically in __half2 (low = older row). Entire pipeline
// (median + residual fma) in packed fp16; single h2->float2 convert before
// the fp32 store. No fp32 row state carried at all -> fits 64 regs
// spill-free at 4 blocks/SM. Error ~ fp16 quantization ~2.8e-4 << 1e-3.

#define H 256
#define W 256

typedef __half2 h2;

struct Raw { float4 a, b; };

__device__ __forceinline__ unsigned h2u(h2 v) { return *reinterpret_cast<unsigned*>(&v); }
__device__ __forceinline__ h2 u2h(unsigned v) { return *reinterpret_cast<h2*>(&v); }

__device__ __forceinline__ Raw load_raw(const float* __restrict__ img,
                                        int g, int lane) {
    Raw r;
    if (g >= 0 && g < H) {
        const float4* p = reinterpret_cast<const float4*>(img + g * W);
        r.a = p[lane * 2];
        r.b = p[lane * 2 + 1];
    } else {
        r.a = make_float4(0.f, 0.f, 0.f, 0.f);
        r.b = r.a;
    }
    return r;
}

// pack two rows into h2 (low = older row); halos via packed shuffles
__device__ __forceinline__ void pack_pair(const Raw& lo, const Raw& hi,
                                          int lane, h2 P[10]) {
    const float* l = &lo.a.x;
    const float* h = &hi.a.x;
    #pragma unroll
    for (int j = 0; j < 8; ++j) P[j + 1] = __floats2half2_rn(l[j], h[j]);
    unsigned lf = __shfl_up_sync(0xffffffffu, h2u(P[8]), 1);
    unsigned rt = __shfl_down_sync(0xffffffffu, h2u(P[1]), 1);
    P[0] = (lane == 0)  ? u2h(0u) : u2h(lf);
    P[9] = (lane == 31) ? u2h(0u) : u2h(rt);
}

// middle pack = (high half of PAB, low half of PCD) in one byte-permute
__device__ __forceinline__ h2 mid_pack(h2 ab, h2 cd) {
    unsigned r;
    asm("prmt.b32 %0, %1, %2, 0x5432;" : "=r"(r) : "r"(h2u(ab)), "r"(h2u(cd)));
    return u2h(r);
}

// packed (min, med, max) of a vertical triple (both output rows at once)
__device__ __forceinline__ void sort3h(h2 a0, h2 a1, h2 a2,
                                       h2& mn, h2& md, h2& mx) {
    h2 lo = __hmin2(a0, a1);
    h2 hi = __hmax2(a0, a1);
    mn = __hmin2(lo, a2);
    md = __hmin2(__hmax2(a2, lo), hi);
    mx = __hmax2(hi, a2);
}

__device__ __forceinline__ h2 med3h(h2 a, h2 b, h2 c) {
    h2 lo = __hmin2(a, b), hi = __hmax2(a, b);
    return __hmin2(__hmax2(c, lo), hi);
}

__global__ void __launch_bounds__(256, 4)
median_blur_kernel(const float* __restrict__ x, float* __restrict__ out) {
    const int lane = threadIdx.x & 31;
    const int wg   = blockIdx.x * (blockDim.x >> 5) + (threadIdx.x >> 5);
    const int n    = wg >> 5;            // image (32 bands per image)
    const int band = wg & 31;
    const int y0   = band * 8;

    const float* img = x   + (size_t)n * H * W;
    float*       o   = out + (size_t)n * H * W + lane * 8;

    const h2 SCALE = __float2half2_rn(0.2f);

    // carried state: ONLY the packed pair (y-1, y)
    h2 PAB[10];
    {
        Raw tA = load_raw(img, y0 - 1, lane);
        Raw tB = load_raw(img, y0,     lane);
        pack_pair(tA, tB, lane, PAB);
    }

    #pragma unroll
    for (int i = 0; i < 4; ++i) {
        const int y = y0 + 2 * i;

        h2 PCD[10];
        {
            Raw tC = load_raw(img, y + 1, lane);
            Raw tD = load_raw(img, y + 2, lane);   // OOB -> zeros
            pack_pair(tC, tD, lane, PCD);
        }

        // sliding 4-column window of packed vertical triples
        h2 mn[4], md[4], mx[4];
        sort3h(PAB[0], mid_pack(PAB[0], PCD[0]), PCD[0], mn[0], md[0], mx[0]);
        h2 PBCl = mid_pack(PAB[1], PCD[1]);        // running centers pack
        sort3h(PAB[1], PBCl, PCD[1], mn[1], md[1], mx[1]);

        float resA[4], resB[4];
        #pragma unroll
        for (int k = 0; k < 4; ++k) {
            const int c2 = 2 * k + 2, c3 = 2 * k + 3;
            h2 PBC2 = mid_pack(PAB[c2], PCD[c2]);
            sort3h(PAB[c2], PBC2, PCD[c2], mn[2], md[2], mx[2]);
            h2 PBC3 = mid_pack(PAB[c3], PCD[c3]);
            sort3h(PAB[c3], PBC3, PCD[c3], mn[3], md[3], mx[3]);

            // pair-shared horizontal merge (pixels 2k, 2k+1; both rows)
            h2 p  = __hmax2(mn[1], mn[2]);
            h2 A0 = __hmax2(mn[0], p);
            h2 A1 = __hmax2(p, mn[3]);
            h2 q  = __hmin2(mx[1], mx[2]);
            h2 C0 = __hmin2(mx[0], q);
            h2 C1 = __hmin2(q, mx[3]);
            h2 lo = __hmin2(md[1], md[2]);
            h2 hi = __hmax2(md[1], md[2]);
            h2 B0 = __hmin2(__hmax2(md[0], lo), hi);
            h2 B1 = __hmin2(__hmax2(md[3], lo), hi);
            h2 M0 = med3h(A0, B0, C0);
            h2 M1 = med3h(A1, B1, C1);

            // fully packed epilogue: R = x + 0.2*(med - x)
            h2 R0 = __hfma2(SCALE, __hsub2(M0, PBCl), PBCl);
            h2 R1 = __hfma2(SCALE, __hsub2(M1, PBC2), PBC2);
            float2 f0 = __half22float2(R0);
            float2 f1 = __half22float2(R1);
            const int s = (2 * k) & 3;
            resA[s]     = f0.x; resB[s]     = f0.y;
            resA[s + 1] = f1.x; resB[s + 1] = f1.y;

            if (k == 1 || k == 3) {                // 4 pixels/row ready
                const int xo = (k == 1 ? 0 : 4);
                *reinterpret_cast<float4*>(o + (size_t)(y    ) * W + xo) =
                    make_float4(resA[0], resA[1], resA[2], resA[3]);
                *reinterpret_cast<float4*>(o + (size_t)(y + 1) * W + xo) =
                    make_float4(resB[0], resB[1], resB[2], resB[3]);
            }

            // slide window by 2 (renamed under full unroll)
            mn[0] = mn[2]; md[0] = md[2]; mx[0] = mx[2];
            mn[1] = mn[3]; md[1] = md[3]; mx[1] = mx[3];
            PBCl = PBC3;
        }

        // roll: next (y'-1, y') = (y+1, y+2)
        #pragma unroll
        for (int j = 0; j < 10; ++j) PAB[j] = PCD[j];
    }
}

extern "C" void kernel_launch(void* const* d_in, const int* in_sizes, int n_in,
                              void* d_out, int out_size) {
    const float* x = (const float*)d_in[0];
    float* out = (float*)d_out;
    // 512 images * 32 bands = 16384 warp-tasks; 8 warps/block -> 2048 blocks
    median_blur_kernel<<<2048, 256>>>(x, out);
}

// round 14
// speedup vs baseline: 1.0842x; 1.0842x over previous
#include <cuda_runtime.h>
#include <cuda_fp16.h>

// MedianBlur: out = x + 0.2*(median3x3(x, zero-pad) - x)
// x: (8, 64, 256, 256) fp32 -> 512 independent 256x256 images.
// Warp = 8-row x 256-col band; lane owns 8 cols. HORIZONTAL half2 packing:
// a row's 10 columns (8 owned + 2 halos) live in 5 h2 regs:
//   P0=(c-1,c0) P1=(c1,c2) P2=(c3,c4) P3=(c5,c6) P4=(c7,c8)
// 3 rolling rows = 15 regs. Vertical sort3 is packed (2 cols/op); the
// merge's misaligned pairs come from PRMT 0x5432 of adjacent packs.
// Full fp16 pipeline incl. residual fma; fp32 store. ~55 live regs ->
// (256,4) spill-free, combining R10's op count with 42%+ occupancy.

#define H 256
#define W 256

typedef __half2 h2;

struct Raw { float4 a, b; };

__device__ __forceinline__ unsigned h2u(h2 v) { return *reinterpret_cast<unsigned*>(&v); }
__device__ __forceinline__ h2 u2h(unsigned v) { return *reinterpret_cast<h2*>(&v); }

__device__ __forceinline__ Raw load_raw(const float* __restrict__ img,
                                        int g, int lane) {
    Raw r;
    if (g >= 0 && g < H) {
        const float4* p = reinterpret_cast<const float4*>(img + g * W);
        r.a = p[lane * 2];
        r.b = p[lane * 2 + 1];
    } else {
        r.a = make_float4(0.f, 0.f, 0.f, 0.f);
        r.b = r.a;
    }
    return r;
}

// raw fp32 row -> 5 horizontal h2 packs (halos via fp32 shuffles)
__device__ __forceinline__ void pack_row(const Raw& t, int lane, h2 P[5]) {
    float lf = __shfl_up_sync(0xffffffffu, t.b.w, 1);    // lane-1's c7
    float rt = __shfl_down_sync(0xffffffffu, t.a.x, 1);  // lane+1's c0
    if (lane == 0)  lf = 0.f;
    if (lane == 31) rt = 0.f;
    P[0] = __floats2half2_rn(lf,    t.a.x);
    P[1] = __floats2half2_rn(t.a.y, t.a.z);
    P[2] = __floats2half2_rn(t.a.w, t.b.x);
    P[3] = __floats2half2_rn(t.b.y, t.b.z);
    P[4] = __floats2half2_rn(t.b.w, rt);
}

// (hi half of a, lo half of b) in one byte-permute
__device__ __forceinline__ h2 midp(h2 a, h2 b) {
    unsigned r;
    asm("prmt.b32 %0, %1, %2, 0x5432;" : "=r"(r) : "r"(h2u(a)), "r"(h2u(b)));
    return u2h(r);
}

// packed (min, med, max) of a vertical triple (2 columns at once)
__device__ __forceinline__ void sort3h(h2 a0, h2 a1, h2 a2,
                                       h2& mn, h2& md, h2& mx) {
    h2 lo = __hmin2(a0, a1);
    h2 hi = __hmax2(a0, a1);
    mn = __hmin2(lo, a2);
    md = __hmin2(__hmax2(a2, lo), hi);
    mx = __hmax2(hi, a2);
}

__device__ __forceinline__ h2 med3h(h2 a, h2 b, h2 c) {
    h2 lo = __hmin2(a, b), hi = __hmax2(a, b);
    return __hmin2(__hmax2(c, lo), hi);
}

__global__ void __launch_bounds__(256, 4)
median_blur_kernel(const float* __restrict__ x, float* __restrict__ out) {
    const int lane = threadIdx.x & 31;
    const int wg   = blockIdx.x * (blockDim.x >> 5) + (threadIdx.x >> 5);
    const int n    = wg >> 5;            // image (32 bands per image)
    const int band = wg & 31;
    const int y0   = band * 8;

    const float* img = x   + (size_t)n * H * W;
    float*       o   = out + (size_t)n * H * W + lane * 8;

    const h2 SCALE = __float2half2_rn(0.2f);

    h2 r0[5], r1[5], r2[5];
    {
        Raw t0 = load_raw(img, y0 - 1, lane);
        Raw t1 = load_raw(img, y0,     lane);
        pack_row(t0, lane, r0);
        pack_row(t1, lane, r1);
    }
    Raw pre = load_raw(img, y0 + 1, lane);    // y0+1 <= 249, in range

    #pragma unroll
    for (int i = 0; i < 8; ++i) {
        const int y = y0 + i;

        pack_row(pre, lane, r2);
        pre = load_raw(img, y + 2, lane);     // next row, OOB -> zeros

        // packed vertical sort3 of all 5 column-pair packs
        h2 MN[5], MD[5], MX[5];
        #pragma unroll
        for (int j = 0; j < 5; ++j)
            sort3h(r0[j], r1[j], r2[j], MN[j], MD[j], MX[j]);

        // 4 output pairs; pair i covers output cols (2i, 2i+1)
        float res[8];
        #pragma unroll
        for (int k = 0; k < 4; ++k) {
            h2 mMN = midp(MN[k], MN[k + 1]);
            h2 mMX = midp(MX[k], MX[k + 1]);
            h2 mMD = midp(MD[k], MD[k + 1]);
            h2 A = __hmax2(__hmax2(MN[k], mMN), MN[k + 1]);
            h2 C = __hmin2(__hmin2(MX[k], mMX), MX[k + 1]);
            h2 B = med3h(MD[k], MD[k + 1], mMD);
            h2 M = med3h(A, B, C);

            h2 X = midp(r1[k], r1[k + 1]);          // fp16 centers
            h2 R = __hfma2(SCALE, __hsub2(M, X), X);
            float2 f = __half22float2(R);
            res[2 * k]     = f.x;
            res[2 * k + 1] = f.y;
        }

        float4* op = reinterpret_cast<float4*>(o + (size_t)y * W);
        op[0] = make_float4(res[0], res[1], res[2], res[3]);
        op[1] = make_float4(res[4], res[5], res[6], res[7]);

        #pragma unroll
        for (int j = 0; j < 5; ++j) { r0[j] = r1[j]; r1[j] = r2[j]; }
    }
}

extern "C" void kernel_launch(void* const* d_in, const int* in_sizes, int n_in,
                              void* d_out, int out_size) {
    const float* x = (const float*)d_in[0];
    float* out = (float*)d_out;
    // 512 images * 32 bands = 16384 warp-tasks; 8 warps/block -> 2048 blocks
    median_blur_kernel<<<2048, 256>>>(x, out);
}

// round 15
// speedup vs baseline: 1.1256x; 1.0382x over previous
#include <cuda_runtime.h>
#include <cuda_fp16.h>

// MedianBlur: out = x + 0.2*(median3x3(x, zero-pad) - x)
// x: (8, 64, 256, 256) fp32 -> 512 independent 256x256 images.
// Warp = 8-row x 256-col band; lane owns 8 cols. Horizontal half2 packing:
// row's 10 cols (8 owned + 2 halos) in 5 h2 regs. Vertical sort3 packed
// (2 cols/op); merge misaligned pairs via PRMT 0x5432. FULLY PIPELINED:
// raw LDG 2 iterations ahead, SHFL+cvt packing 1 iteration ahead, so the
// ~100-cyc shuffle/convert latency never sits on the compute critical path.

#define H 256
#define W 256

typedef __half2 h2;

struct Raw { float4 a, b; };

__device__ __forceinline__ unsigned h2u(h2 v) { return *reinterpret_cast<unsigned*>(&v); }
__device__ __forceinline__ h2 u2h(unsigned v) { return *reinterpret_cast<h2*>(&v); }

__device__ __forceinline__ Raw load_raw(const float* __restrict__ img,
                                        int g, int lane) {
    Raw r;
    if (g >= 0 && g < H) {
        const float4* p = reinterpret_cast<const float4*>(img + g * W);
        r.a = p[lane * 2];
        r.b = p[lane * 2 + 1];
    } else {
        r.a = make_float4(0.f, 0.f, 0.f, 0.f);
        r.b = r.a;
    }
    return r;
}

// raw fp32 row -> 5 horizontal h2 packs (halos via fp32 shuffles)
__device__ __forceinline__ void pack_row(const Raw& t, int lane, h2 P[5]) {
    float lf = __shfl_up_sync(0xffffffffu, t.b.w, 1);    // lane-1's c7
    float rt = __shfl_down_sync(0xffffffffu, t.a.x, 1);  // lane+1's c0
    if (lane == 0)  lf = 0.f;
    if (lane == 31) rt = 0.f;
    P[0] = __floats2half2_rn(lf,    t.a.x);
    P[1] = __floats2half2_rn(t.a.y, t.a.z);
    P[2] = __floats2half2_rn(t.a.w, t.b.x);
    P[3] = __floats2half2_rn(t.b.y, t.b.z);
    P[4] = __floats2half2_rn(t.b.w, rt);
}

// (hi half of a, lo half of b) in one byte-permute
__device__ __forceinline__ h2 midp(h2 a, h2 b) {
    unsigned r;
    asm("prmt.b32 %0, %1, %2, 0x5432;" : "=r"(r) : "r"(h2u(a)), "r"(h2u(b)));
    return u2h(r);
}

// packed (min, med, max) of a vertical triple (2 columns at once)
__device__ __forceinline__ void sort3h(h2 a0, h2 a1, h2 a2,
                                       h2& mn, h2& md, h2& mx) {
    h2 lo = __hmin2(a0, a1);
    h2 hi = __hmax2(a0, a1);
    mn = __hmin2(lo, a2);
    md = __hmin2(__hmax2(a2, lo), hi);
    mx = __hmax2(hi, a2);
}

__device__ __forceinline__ h2 med3h(h2 a, h2 b, h2 c) {
    h2 lo = __hmin2(a, b), hi = __hmax2(a, b);
    return __hmin2(__hmax2(c, lo), hi);
}

__global__ void __launch_bounds__(256, 4)
median_blur_kernel(const float* __restrict__ x, float* __restrict__ out) {
    const int lane = threadIdx.x & 31;
    const int wg   = blockIdx.x * (blockDim.x >> 5) + (threadIdx.x >> 5);
    const int n    = wg >> 5;            // image (32 bands per image)
    const int band = wg & 31;
    const int y0   = band * 8;

    const float* img = x   + (size_t)n * H * W;
    float*       o   = out + (size_t)n * H * W + lane * 8;

    const h2 SCALE = __float2half2_rn(0.2f);

    // pipeline state: packed rows y-1..y+1, packed-next y+2, raw y+2 staged
    h2 r0[5], r1[5], r2[5], r3[5];
    Raw rawPre;
    {
        Raw t0 = load_raw(img, y0 - 1, lane);
        Raw t1 = load_raw(img, y0,     lane);
        Raw t2 = load_raw(img, y0 + 1, lane);
        pack_row(t0, lane, r0);
        pack_row(t1, lane, r1);
        pack_row(t2, lane, r2);
        rawPre = load_raw(img, y0 + 2, lane);
    }

    #pragma unroll
    for (int i = 0; i < 8; ++i) {
        const int y = y0 + i;

        // stage 1: prefetch raw row y+3 (consumed 2 iterations from now)
        Raw rawNext = load_raw(img, y + 3, lane);   // OOB -> zeros

        // stage 2: pack row y+2 (raw loaded last iteration); results used
        // next iteration, so SHFL(26) + cvt(~20) latency is fully hidden
        pack_row(rawPre, lane, r3);

        // stage 3: compute output row y from already-packed r0,r1,r2
        h2 MN[5], MD[5], MX[5];
        #pragma unroll
        for (int j = 0; j < 5; ++j)
            sort3h(r0[j], r1[j], r2[j], MN[j], MD[j], MX[j]);

        float res[8];
        #pragma unroll
        for (int k = 0; k < 4; ++k) {
            h2 t1m = __hmax2(MN[k], MN[k + 1]);
            h2 A   = __hmax2(t1m, midp(MN[k], MN[k + 1]));
            h2 t2m = __hmin2(MX[k], MX[k + 1]);
            h2 C   = __hmin2(t2m, midp(MX[k], MX[k + 1]));
            h2 B   = med3h(MD[k], MD[k + 1], midp(MD[k], MD[k + 1]));
            h2 M   = med3h(A, B, C);

            h2 X = midp(r1[k], r1[k + 1]);          // fp16 centers
            h2 R = __hfma2(SCALE, __hsub2(M, X), X);
            float2 f = __half22float2(R);
            res[2 * k]     = f.x;
            res[2 * k + 1] = f.y;
        }

        float4* op = reinterpret_cast<float4*>(o + (size_t)y * W);
        op[0] = make_float4(res[0], res[1], res[2], res[3]);
        op[1] = make_float4(res[4], res[5], res[6], res[7]);

        // roll pipeline (renamed away under full unroll)
        #pragma unroll
        for (int j = 0; j < 5; ++j) { r0[j] = r1[j]; r1[j] = r2[j]; r2[j] = r3[j]; }
        rawPre = rawNext;
    }
}

extern "C" void kernel_launch(void* const* d_in, const int* in_sizes, int n_in,
                              void* d_out, int out_size) {
    const float* x = (const float*)d_in[0];
    float* out = (float*)d_out;
    // 512 images * 32 bands = 16384 warp-tasks; 8 warps/block -> 2048 blocks
    median_blur_kernel<<<2048, 256>>>(x, out);
}

// round 16
// speedup vs baseline: 1.1322x; 1.0059x over previous
#include <cuda_runtime.h>
#include <cuda_fp16.h>
#include <cstdint>

// MedianBlur: out = x + 0.2*(median3x3(x, zero-pad) - x)
// x: (8, 64, 256, 256) fp32 -> 512 independent 256x256 images.
// Warp = 8-row x 256-col band; lane owns 8 cols. Horizontal half2 packing
// (row's 10 cols in 5 h2 regs); packed vertical sort3 + PRMT merge.
// MEMORY: per-warp 4-slot smem ring fed by cp.async.cg (LDGSTS), 3 row-loads
// in flight per warp (~3KB) -> ~4x the in-flight bytes of the LDG version,
// unclogging the DRAM latency/MLP knee that pinned HBM at 60%.

#define H 256
#define W 256

typedef __half2 h2;

__device__ __forceinline__ unsigned h2u(h2 v) { return *reinterpret_cast<unsigned*>(&v); }
__device__ __forceinline__ h2 u2h(unsigned v) { return *reinterpret_cast<h2*>(&v); }

// stage one 1024B image row (or zeros if g OOB / unneeded) into a smem slot
__device__ __forceinline__ void cp_row(uint32_t slot, const float* __restrict__ img,
                                       int g, int lane) {
    int gc = min(max(g, 0), H - 1);                       // valid address always
    const char* src = reinterpret_cast<const char*>(img + (size_t)gc * W) + lane * 16;
    unsigned sz = (g >= 0 && g < H) ? 16u : 0u;           // 0 => zfill
    asm volatile("cp.async.cg.shared.global [%0], [%1], 16, %2;"
                 :: "r"(slot + lane * 16), "l"(src), "r"(sz));
    asm volatile("cp.async.cg.shared.global [%0], [%1], 16, %2;"
                 :: "r"(slot + 512 + lane * 16), "l"(src + 512), "r"(sz));
    asm volatile("cp.async.commit_group;" ::: "memory");
}

#define CP_WAIT(N) asm volatile("cp.async.wait_group %0;" :: "n"(N) : "memory")

// read a staged row from smem, convert to 5 horizontal h2 packs w/ halos
__device__ __forceinline__ void pack_slot(uint32_t slot, int lane, h2 P[5]) {
    float4 a, b;
    asm volatile("ld.shared.v4.f32 {%0,%1,%2,%3}, [%4];"
                 : "=f"(a.x), "=f"(a.y), "=f"(a.z), "=f"(a.w)
                 : "r"(slot + lane * 32));
    asm volatile("ld.shared.v4.f32 {%0,%1,%2,%3}, [%4];"
                 : "=f"(b.x), "=f"(b.y), "=f"(b.z), "=f"(b.w)
                 : "r"(slot + lane * 32 + 16));
    float lf = __shfl_up_sync(0xffffffffu, b.w, 1);
    float rt = __shfl_down_sync(0xffffffffu, a.x, 1);
    if (lane == 0)  lf = 0.f;
    if (lane == 31) rt = 0.f;
    P[0] = __floats2half2_rn(lf,  a.x);
    P[1] = __floats2half2_rn(a.y, a.z);
    P[2] = __floats2half2_rn(a.w, b.x);
    P[3] = __floats2half2_rn(b.y, b.z);
    P[4] = __floats2half2_rn(b.w, rt);
}

__device__ __forceinline__ h2 midp(h2 a, h2 b) {
    unsigned r;
    asm("prmt.b32 %0, %1, %2, 0x5432;" : "=r"(r) : "r"(h2u(a)), "r"(h2u(b)));
    return u2h(r);
}

__device__ __forceinline__ void sort3h(h2 a0, h2 a1, h2 a2,
                                       h2& mn, h2& md, h2& mx) {
    h2 lo = __hmin2(a0, a1);
    h2 hi = __hmax2(a0, a1);
    mn = __hmin2(lo, a2);
    md = __hmin2(__hmax2(a2, lo), hi);
    mx = __hmax2(hi, a2);
}

__device__ __forceinline__ h2 med3h(h2 a, h2 b, h2 c) {
    h2 lo = __hmin2(a, b), hi = __hmax2(a, b);
    return __hmin2(__hmax2(c, lo), hi);
}

__global__ void __launch_bounds__(256, 4)
median_blur_kernel(const float* __restrict__ x, float* __restrict__ out) {
    __shared__ float smem[8 * 4 * 256];        // 8 warps x 4 slots x 1KB = 32KB

    const int lane = threadIdx.x & 31;
    const int wib  = threadIdx.x >> 5;
    const int wg   = blockIdx.x * 8 + wib;
    const int n    = wg >> 5;                  // image (32 bands per image)
    const int band = wg & 31;
    const int y0   = band * 8;

    const float* img = x   + (size_t)n * H * W;
    float*       o   = out + (size_t)n * H * W + lane * 8;

    const uint32_t sbase =
        (uint32_t)__cvta_generic_to_shared(smem) + wib * 4096u;
    const h2 SCALE = __float2half2_rn(0.2f);

    // prologue: fill 4 slots (rows y0-1 .. y0+2), groups 1..4
    cp_row(sbase + 0 * 1024, img, y0 - 1, lane);
    cp_row(sbase + 1 * 1024, img, y0,     lane);
    cp_row(sbase + 2 * 1024, img, y0 + 1, lane);
    cp_row(sbase + 3 * 1024, img, y0 + 2, lane);

    h2 r0[5], r1[5], r2[5], r3[5];
    CP_WAIT(1);                                // rows y0-1..y0+1 arrived
    __syncwarp();
    pack_slot(sbase + 0 * 1024, lane, r0);
    pack_slot(sbase + 1 * 1024, lane, r1);
    pack_slot(sbase + 2 * 1024, lane, r2);
    __syncwarp();
    // refill freed slots: rows y0+3, y0+4, y0+5 (groups 5..7)
    cp_row(sbase + 0 * 1024, img, y0 + 3, lane);
    cp_row(sbase + 1 * 1024, img, y0 + 4, lane);
    cp_row(sbase + 2 * 1024, img, y0 + 5, lane);

    #pragma unroll
    for (int i = 0; i < 8; ++i) {
        const int y = y0 + i;
        const uint32_t slot = sbase + (uint32_t)((i + 3) & 3) * 1024u;

        // row y+2 (group 4+i) has arrived once pending <= 3
        CP_WAIT(3);
        __syncwarp();
        pack_slot(slot, lane, r3);             // stage for next iteration
        __syncwarp();                          // all lanes done reading slot
        {
            // reuse slot for row y+6; rows beyond the band's halo are zfill
            int g = y + 6;
            cp_row(slot, img, (g <= y0 + 8) ? g : -1, lane);
        }

        // compute output row y from packed rows y-1, y, y+1
        h2 MN[5], MD[5], MX[5];
        #pragma unroll
        for (int j = 0; j < 5; ++j)
            sort3h(r0[j], r1[j], r2[j], MN[j], MD[j], MX[j]);

        float res[8];
        #pragma unroll
        for (int k = 0; k < 4; ++k) {
            h2 A = __hmax2(__hmax2(MN[k], MN[k + 1]), midp(MN[k], MN[k + 1]));
            h2 C = __hmin2(__hmin2(MX[k], MX[k + 1]), midp(MX[k], MX[k + 1]));
            h2 B = med3h(MD[k], MD[k + 1], midp(MD[k], MD[k + 1]));
            h2 M = med3h(A, B, C);

            h2 X = midp(r1[k], r1[k + 1]);      // fp16 centers
            h2 R = __hfma2(SCALE, __hsub2(M, X), X);
            float2 f = __half22float2(R);
            res[2 * k]     = f.x;
            res[2 * k + 1] = f.y;
        }

        float4* op = reinterpret_cast<float4*>(o + (size_t)y * W);
        op[0] = make_float4(res[0], res[1], res[2], res[3]);
        op[1] = make_float4(res[4], res[5], res[6], res[7]);

        #pragma unroll
        for (int j = 0; j < 5; ++j) { r0[j] = r1[j]; r1[j] = r2[j]; r2[j] = r3[j]; }
    }

    // drain outstanding async copies before exit
    asm volatile("cp.async.wait_all;" ::: "memory");
}

extern "C" void kernel_launch(void* const* d_in, const int* in_sizes, int n_in,
                              void* d_out, int out_size) {
    const float* x = (const float*)d_in[0];
    float* out = (float*)d_out;
    // 512 images * 32 bands = 16384 warp-tasks; 8 warps/block -> 2048 blocks
    median_blur_kernel<<<2048, 256>>>(x, out);
}